// round 14
// baseline (speedup 1.0000x reference)
#include <cuda_runtime.h>
#include <cstdint>

#define BB 4
#define HH 8
#define SS 2048
#define DD 64
#define BM 64          // query rows per CTA
#define BN 128         // key cols per tile
#define NT (SS / BN)   // 16 tiles
#define THREADS 512

#define KT_STRIDE 68   // K tile row stride: frag banks 4g+tg distinct
#define VT_STRIDE 72   // V tile row stride: frag banks 8tg+g distinct
#define QS_STRIDE 68
#define PB_STRIDE 68

// smem floats: kt[128][68]=8704 + vt[128][72]=9216 + qs[64][68]=4352 = 22272 (89KB)
// pbuf (16 warps x 16 rows x 68 = 17408) reuses kt+vt; stats reuse qs.
#define SMEM_FLOATS (128 * KT_STRIDE + 128 * VT_STRIDE + BM * QS_STRIDE)

__device__ __forceinline__ uint32_t f2tf(float f) {
    uint32_t r;
    asm("cvt.rna.tf32.f32 %0, %1;" : "=r"(r) : "f"(f));
    return r;
}

__device__ __forceinline__ void mma_tf32(float acc[4],
                                         uint32_t a0, uint32_t a1, uint32_t a2, uint32_t a3,
                                         uint32_t b0, uint32_t b1) {
    asm volatile(
        "mma.sync.aligned.m16n8k8.row.col.f32.tf32.tf32.f32 "
        "{%0,%1,%2,%3}, {%4,%5,%6,%7}, {%8,%9}, {%0,%1,%2,%3};"
        : "+f"(acc[0]), "+f"(acc[1]), "+f"(acc[2]), "+f"(acc[3])
        : "r"(a0), "r"(a1), "r"(a2), "r"(a3), "r"(b0), "r"(b1));
}

__global__ __launch_bounds__(THREADS, 1)
void attn_flash64_kernel(const float* __restrict__ Q,
                         const float* __restrict__ K,
                         const float* __restrict__ V,
                         const int* __restrict__ mask,     // bool as int32
                         const float* __restrict__ edge,
                         float* __restrict__ out_ctx,
                         float* __restrict__ out_attn,
                         float* __restrict__ out_scores)
{
    extern __shared__ float smem[];
    float* kt = smem;                            // [128][KT_STRIDE] tf32 bits
    float* vt = kt + 128 * KT_STRIDE;            // [128][VT_STRIDE] tf32 bits
    float* qs = vt + 128 * VT_STRIDE;            // [64][QS_STRIDE]
    uint32_t* ktu = (uint32_t*)kt;
    uint32_t* vtu = (uint32_t*)vt;

    const int tid  = threadIdx.x;
    const int lane = tid & 31;
    const int w    = tid >> 5;          // 0..15
    const int rb   = w >> 2;            // row block 0..3 (16 rows each)
    const int ksl  = w & 3;             // key slice 0..3 (32 keys each)
    const int g    = lane >> 2;         // 0..7
    const int tg   = lane & 3;          // 0..3

    const int bh    = blockIdx.x;       // 0..31
    const int b     = bh >> 3;
    const int qbase = blockIdx.y * BM;

    const size_t bhS = (size_t)bh * SS;
    const float* Qg = Q + (bhS + qbase) * DD;
    const float* Kg = K + bhS * DD;
    const float* Vg = V + bhS * DD;
    const int*   Mg = mask + (bhS + qbase) * SS;
    const float* Eg = edge + ((size_t)b * SS + qbase) * SS;

    // ---- Load Q tile (64x64) ----
    #pragma unroll
    for (int p = 0; p < 2; ++p) {
        int f = tid + p * THREADS;
        int row = f >> 4, d4 = (f & 15) << 2;
        *(float4*)(qs + row * QS_STRIDE + d4) = ((const float4*)Qg)[f];
    }
    __syncthreads();

    // ---- Preload Q fragments (tf32); warp rows: rb*16 + g, + g+8 ----
    uint32_t qa[8][4];
    {
        const float* q0 = qs + (rb * 16 + g) * QS_STRIDE;
        const float* q1 = qs + (rb * 16 + g + 8) * QS_STRIDE;
        #pragma unroll
        for (int ks = 0; ks < 8; ++ks) {
            int kc = ks * 8 + tg;
            qa[ks][0] = f2tf(q0[kc]);
            qa[ks][1] = f2tf(q1[kc]);
            qa[ks][2] = f2tf(q0[kc + 4]);
            qa[ks][3] = f2tf(q1[kc + 4]);
        }
    }

    const float scale = 0.125f;  // 1/sqrt(64)
    const int nbase = ksl * 32;  // warp's 32-key slice within 128-key tile

    // Online softmax state (rows rb*16+g and rb*16+g+8, warp's key slice)
    float m_g = -1e30f, m_g8 = -1e30f;
    float z_g = 0.f, z_g8 = 0.f;
    float cacc[8][4];
    #pragma unroll
    for (int n = 0; n < 8; ++n)
        cacc[n][0] = cacc[n][1] = cacc[n][2] = cacc[n][3] = 0.f;

    for (int t = 0; t < NT; ++t) {
        __syncthreads();
        // Load K and V tiles (128x64), converting to tf32 bits at store
        const float4* ksrc = (const float4*)(Kg + (size_t)t * BN * DD);
        const float4* vsrc = (const float4*)(Vg + (size_t)t * BN * DD);
        #pragma unroll
        for (int p = 0; p < 4; ++p) {
            int f = tid + p * THREADS;
            int row = f >> 4, d4 = (f & 15) << 2;
            float4 kv = ksrc[f];
            float4 vv = vsrc[f];
            uint4 ku = make_uint4(f2tf(kv.x), f2tf(kv.y), f2tf(kv.z), f2tf(kv.w));
            uint4 vu = make_uint4(f2tf(vv.x), f2tf(vv.y), f2tf(vv.z), f2tf(vv.w));
            *(uint4*)(ktu + row * KT_STRIDE + d4) = ku;
            *(uint4*)(vtu + row * VT_STRIDE + d4) = vu;
        }
        __syncthreads();

        // ---- QK^T for this warp's 32 keys ----
        float acc[4][4];
        #pragma unroll
        for (int nb = 0; nb < 4; ++nb)
            acc[nb][0] = acc[nb][1] = acc[nb][2] = acc[nb][3] = 0.f;
        #pragma unroll
        for (int ks = 0; ks < 8; ++ks) {
            int kc = ks * 8 + tg;
            #pragma unroll
            for (int nb = 0; nb < 4; ++nb) {
                int key = nbase + nb * 8 + g;
                uint32_t b0 = ktu[key * KT_STRIDE + kc];
                uint32_t b1 = ktu[key * KT_STRIDE + kc + 4];
                mma_tf32(acc[nb], qa[ks][0], qa[ks][1], qa[ks][2], qa[ks][3], b0, b1);
            }
        }

        // ---- Epilogue: scale + edge + mask; write scores ----
        #pragma unroll
        for (int nb = 0; nb < 4; ++nb) {
            int col = t * BN + nbase + nb * 8 + 2 * tg;
            #pragma unroll
            for (int rr = 0; rr < 2; ++rr) {
                int r = rb * 16 + g + rr * 8;
                float2 e = *(const float2*)(Eg + (size_t)r * SS + col);
                int2  mv = *(const int2*)(Mg + (size_t)r * SS + col);
                float s0 = acc[nb][rr*2+0] * scale + e.x;
                float s1 = acc[nb][rr*2+1] * scale + e.y;
                s0 = mv.x ? -1e9f : s0;
                s1 = mv.y ? -1e9f : s1;
                acc[nb][rr*2+0] = s0;
                acc[nb][rr*2+1] = s1;
                *(float2*)(out_scores + (bhS + qbase + r) * SS + col) = make_float2(s0, s1);
            }
        }

        // ---- Online softmax update (per warp slice) ----
        float tm_g  = fmaxf(fmaxf(acc[0][0], acc[0][1]), fmaxf(acc[1][0], acc[1][1]));
        float tm_g8 = fmaxf(fmaxf(acc[0][2], acc[0][3]), fmaxf(acc[1][2], acc[1][3]));
        tm_g  = fmaxf(tm_g,  fmaxf(fmaxf(acc[2][0], acc[2][1]), fmaxf(acc[3][0], acc[3][1])));
        tm_g8 = fmaxf(tm_g8, fmaxf(fmaxf(acc[2][2], acc[2][3]), fmaxf(acc[3][2], acc[3][3])));
        tm_g  = fmaxf(tm_g,  __shfl_xor_sync(0xFFFFFFFFu, tm_g,  1));
        tm_g  = fmaxf(tm_g,  __shfl_xor_sync(0xFFFFFFFFu, tm_g,  2));
        tm_g8 = fmaxf(tm_g8, __shfl_xor_sync(0xFFFFFFFFu, tm_g8, 1));
        tm_g8 = fmaxf(tm_g8, __shfl_xor_sync(0xFFFFFFFFu, tm_g8, 2));

        float nm_g  = fmaxf(m_g,  tm_g);
        float nm_g8 = fmaxf(m_g8, tm_g8);
        float f_g   = __expf(m_g  - nm_g);
        float f_g8  = __expf(m_g8 - nm_g8);
        m_g = nm_g; m_g8 = nm_g8;

        float zs_g = 0.f, zs_g8 = 0.f;
        #pragma unroll
        for (int nb = 0; nb < 4; ++nb) {
            acc[nb][0] = __expf(acc[nb][0] - m_g);
            acc[nb][1] = __expf(acc[nb][1] - m_g);
            acc[nb][2] = __expf(acc[nb][2] - m_g8);
            acc[nb][3] = __expf(acc[nb][3] - m_g8);
            zs_g  += acc[nb][0] + acc[nb][1];
            zs_g8 += acc[nb][2] + acc[nb][3];
        }
        zs_g  += __shfl_xor_sync(0xFFFFFFFFu, zs_g,  1);
        zs_g  += __shfl_xor_sync(0xFFFFFFFFu, zs_g,  2);
        zs_g8 += __shfl_xor_sync(0xFFFFFFFFu, zs_g8, 1);
        zs_g8 += __shfl_xor_sync(0xFFFFFFFFu, zs_g8, 2);
        z_g  = z_g  * f_g  + zs_g;
        z_g8 = z_g8 * f_g8 + zs_g8;

        #pragma unroll
        for (int n = 0; n < 8; ++n) {
            cacc[n][0] *= f_g;  cacc[n][1] *= f_g;
            cacc[n][2] *= f_g8; cacc[n][3] *= f_g8;
        }

        // ---- PV: P C-frag -> A-frag via quad shuffles, mma over dims ----
        #pragma unroll
        for (int c = 0; c < 4; ++c) {
            int src0 = (g << 2) + (tg >> 1);
            int src1 = src0 + 2;
            float v00 = __shfl_sync(0xFFFFFFFFu, acc[c][0], src0);
            float v01 = __shfl_sync(0xFFFFFFFFu, acc[c][1], src0);
            float v10 = __shfl_sync(0xFFFFFFFFu, acc[c][2], src0);
            float v11 = __shfl_sync(0xFFFFFFFFu, acc[c][3], src0);
            float v20 = __shfl_sync(0xFFFFFFFFu, acc[c][0], src1);
            float v21 = __shfl_sync(0xFFFFFFFFu, acc[c][1], src1);
            float v30 = __shfl_sync(0xFFFFFFFFu, acc[c][2], src1);
            float v31 = __shfl_sync(0xFFFFFFFFu, acc[c][3], src1);
            bool odd = (tg & 1);
            uint32_t a0 = f2tf(odd ? v01 : v00);
            uint32_t a1 = f2tf(odd ? v11 : v10);
            uint32_t a2 = f2tf(odd ? v21 : v20);
            uint32_t a3 = f2tf(odd ? v31 : v30);

            int kr0 = nbase + c * 8 + tg;
            const uint32_t* v0p = vtu + kr0 * VT_STRIDE + g;
            const uint32_t* v1p = vtu + (kr0 + 4) * VT_STRIDE + g;
            #pragma unroll
            for (int n = 0; n < 8; ++n) {
                mma_tf32(cacc[n], a0, a1, a2, a3, v0p[n * 8], v1p[n * 8]);
            }
        }
    }

    __syncthreads();

    // ---- Write per-warp partials + stats (pbuf reuses kt+vt; stats reuse qs) ----
    float* pbuf   = kt;          // [16 warps][16 rows][PB_STRIDE] = 17408 floats
    float* sm_m   = qs;          // [16][16]
    float* sm_z   = qs + 256;    // [16][16]
    float* row_m  = qs + 512;    // [64]
    float* row_iz = qs + 576;    // [64]

    #pragma unroll
    for (int n = 0; n < 8; ++n) {
        pbuf[(w * 16 + g)     * PB_STRIDE + n * 8 + 2 * tg]     = cacc[n][0];
        pbuf[(w * 16 + g)     * PB_STRIDE + n * 8 + 2 * tg + 1] = cacc[n][1];
        pbuf[(w * 16 + g + 8) * PB_STRIDE + n * 8 + 2 * tg]     = cacc[n][2];
        pbuf[(w * 16 + g + 8) * PB_STRIDE + n * 8 + 2 * tg + 1] = cacc[n][3];
    }
    if (tg == 0) {
        sm_m[w * 16 + g]     = m_g;  sm_m[w * 16 + g + 8] = m_g8;
        sm_z[w * 16 + g]     = z_g;  sm_z[w * 16 + g + 8] = z_g8;
    }
    __syncthreads();

    // ---- Combine 4 key-slice warps per row -> ctx ----
    {
        int r  = tid >> 3;            // 0..63
        int c  = tid & 7;             // 0..7
        int d0 = c * 8;
        int lrb = r >> 4, lr = r & 15;

        float m = -1e30f;
        #pragma unroll
        for (int s = 0; s < 4; ++s)
            m = fmaxf(m, sm_m[(lrb * 4 + s) * 16 + lr]);
        float zt = 0.f;
        float val[8] = {0.f,0.f,0.f,0.f,0.f,0.f,0.f,0.f};
        #pragma unroll
        for (int s = 0; s < 4; ++s) {
            int ww = lrb * 4 + s;
            float ew = __expf(sm_m[ww * 16 + lr] - m);
            zt += sm_z[ww * 16 + lr] * ew;
            const float* pp = pbuf + (ww * 16 + lr) * PB_STRIDE + d0;
            #pragma unroll
            for (int j = 0; j < 8; ++j) val[j] += pp[j] * ew;
        }
        float iz = 1.0f / zt;
        float* op = out_ctx + (bhS + qbase + r) * DD + d0;
        *(float4*)(op)     = make_float4(val[0]*iz, val[1]*iz, val[2]*iz, val[3]*iz);
        *(float4*)(op + 4) = make_float4(val[4]*iz, val[5]*iz, val[6]*iz, val[7]*iz);
        if (c == 0) { row_m[r] = m; row_iz[r] = iz; }
    }
    __syncthreads();

    // ---- Phase C: attn = exp(scores - m) * 1/Z (scores L2-hot) ----
    {
        int r = tid >> 3;
        int c = tid & 7;
        float m  = row_m[r];
        float iz = row_iz[r];
        const float4* sv = (const float4*)(out_scores + (bhS + qbase + r) * SS);
        float4*       av = (float4*)(out_attn  + (bhS + qbase + r) * SS);
        #pragma unroll 4
        for (int k4 = c; k4 < SS / 4; k4 += 8) {
            float4 x = sv[k4];
            x.x = __expf(x.x - m) * iz;
            x.y = __expf(x.y - m) * iz;
            x.z = __expf(x.z - m) * iz;
            x.w = __expf(x.w - m) * iz;
            av[k4] = x;
        }
    }
}

extern "C" void kernel_launch(void* const* d_in, const int* in_sizes, int n_in,
                              void* d_out, int out_size)
{
    (void)in_sizes; (void)n_in; (void)out_size;
    const float* Q = (const float*)d_in[0];
    const float* K = (const float*)d_in[1];
    const float* V = (const float*)d_in[2];
    const int* mask = (const int*)d_in[3];
    const float* edge = (const float*)d_in[4];

    float* ctx = (float*)d_out;
    const size_t n_ctx  = (size_t)BB * HH * SS * DD;
    const size_t n_attn = (size_t)BB * HH * SS * SS;
    float* attn   = ctx + n_ctx;
    float* scores = attn + n_attn;

    const size_t smem_bytes = (size_t)SMEM_FLOATS * sizeof(float);
    cudaFuncSetAttribute(attn_flash64_kernel,
                         cudaFuncAttributeMaxDynamicSharedMemorySize,
                         (int)smem_bytes);

    dim3 grid(BB * HH, SS / BM);   // (32, 32); x fastest -> K/V + edge hot in L2
    attn_flash64_kernel<<<grid, THREADS, smem_bytes>>>(Q, K, V, mask, edge, ctx, attn, scores);
}

// round 15
// speedup vs baseline: 1.0186x; 1.0186x over previous
#include <cuda_runtime.h>
#include <cstdint>

#define BB 4
#define HH 8
#define SS 2048
#define DD 64
#define BM 64          // query rows per CTA
#define BN 128         // key cols per tile
#define NT (SS / BN)   // 16 tiles
#define THREADS 512

#define KT_STRIDE 68   // K tile row stride: frag banks 4g+tg distinct
#define VT_STRIDE 72   // V tile row stride: frag banks 8tg+g distinct
#define QS_STRIDE 68
#define PB_STRIDE 68

// smem floats: kt[128][68]=8704 + vt[128][72]=9216 + qs[64][68]=4352 = 22272 (89KB)
// pbuf (16 warps x 16 rows x 68 = 17408) reuses kt+vt; stats reuse qs.
#define SMEM_FLOATS (128 * KT_STRIDE + 128 * VT_STRIDE + BM * QS_STRIDE)

__device__ __forceinline__ uint32_t f2tf(float f) {
    uint32_t r;
    asm("cvt.rna.tf32.f32 %0, %1;" : "=r"(r) : "f"(f));
    return r;
}

__device__ __forceinline__ void mma_tf32(float acc[4],
                                         uint32_t a0, uint32_t a1, uint32_t a2, uint32_t a3,
                                         uint32_t b0, uint32_t b1) {
    asm volatile(
        "mma.sync.aligned.m16n8k8.row.col.f32.tf32.tf32.f32 "
        "{%0,%1,%2,%3}, {%4,%5,%6,%7}, {%8,%9}, {%0,%1,%2,%3};"
        : "+f"(acc[0]), "+f"(acc[1]), "+f"(acc[2]), "+f"(acc[3])
        : "r"(a0), "r"(a1), "r"(a2), "r"(a3), "r"(b0), "r"(b1));
}

__global__ __launch_bounds__(THREADS, 1)
void attn_flash64_kernel(const float* __restrict__ Q,
                         const float* __restrict__ K,
                         const float* __restrict__ V,
                         const int* __restrict__ mask,     // bool as int32
                         const float* __restrict__ edge,
                         float* __restrict__ out_ctx,
                         float* __restrict__ out_attn,
                         float* __restrict__ out_scores)
{
    extern __shared__ float smem[];
    float* kt = smem;                            // [128][KT_STRIDE] tf32 bits
    float* vt = kt + 128 * KT_STRIDE;            // [128][VT_STRIDE] tf32 bits
    float* qs = vt + 128 * VT_STRIDE;            // [64][QS_STRIDE]
    uint32_t* ktu = (uint32_t*)kt;
    uint32_t* vtu = (uint32_t*)vt;

    const int tid  = threadIdx.x;
    const int lane = tid & 31;
    const int w    = tid >> 5;          // 0..15
    const int rb   = w >> 2;            // row block 0..3 (16 rows each)
    const int ksl  = w & 3;             // key slice 0..3 (32 keys each)
    const int g    = lane >> 2;         // 0..7
    const int tg   = lane & 3;          // 0..3

    const int bh    = blockIdx.x;       // 0..31
    const int b     = bh >> 3;
    const int qbase = blockIdx.y * BM;

    const size_t bhS = (size_t)bh * SS;
    const float* Qg = Q + (bhS + qbase) * DD;
    const float* Kg = K + bhS * DD;
    const float* Vg = V + bhS * DD;
    const int*   Mg = mask + (bhS + qbase) * SS;
    const float* Eg = edge + ((size_t)b * SS + qbase) * SS;

    // ---- Load Q tile (64x64) ----
    #pragma unroll
    for (int p = 0; p < 2; ++p) {
        int f = tid + p * THREADS;
        int row = f >> 4, d4 = (f & 15) << 2;
        *(float4*)(qs + row * QS_STRIDE + d4) = ((const float4*)Qg)[f];
    }
    __syncthreads();

    // ---- Preload Q fragments (tf32); warp rows: rb*16 + g, + g+8 ----
    uint32_t qa[8][4];
    {
        const float* q0 = qs + (rb * 16 + g) * QS_STRIDE;
        const float* q1 = qs + (rb * 16 + g + 8) * QS_STRIDE;
        #pragma unroll
        for (int ks = 0; ks < 8; ++ks) {
            int kc = ks * 8 + tg;
            qa[ks][0] = f2tf(q0[kc]);
            qa[ks][1] = f2tf(q1[kc]);
            qa[ks][2] = f2tf(q0[kc + 4]);
            qa[ks][3] = f2tf(q1[kc + 4]);
        }
    }

    const float scale = 0.125f;  // 1/sqrt(64)
    const int nbase = ksl * 32;  // warp's 32-key slice within 128-key tile

    // Online softmax state (rows rb*16+g and rb*16+g+8, warp's key slice)
    float m_g = -1e30f, m_g8 = -1e30f;
    float z_g = 0.f, z_g8 = 0.f;
    float cacc[8][4];
    #pragma unroll
    for (int n = 0; n < 8; ++n)
        cacc[n][0] = cacc[n][1] = cacc[n][2] = cacc[n][3] = 0.f;

    for (int t = 0; t < NT; ++t) {
        __syncthreads();
        // Load K and V tiles (128x64), converting to tf32 bits at store
        const float4* ksrc = (const float4*)(Kg + (size_t)t * BN * DD);
        const float4* vsrc = (const float4*)(Vg + (size_t)t * BN * DD);
        #pragma unroll
        for (int p = 0; p < 4; ++p) {
            int f = tid + p * THREADS;
            int row = f >> 4, d4 = (f & 15) << 2;
            float4 kv = ksrc[f];
            float4 vv = vsrc[f];
            uint4 ku = make_uint4(f2tf(kv.x), f2tf(kv.y), f2tf(kv.z), f2tf(kv.w));
            uint4 vu = make_uint4(f2tf(vv.x), f2tf(vv.y), f2tf(vv.z), f2tf(vv.w));
            *(uint4*)(ktu + row * KT_STRIDE + d4) = ku;
            *(uint4*)(vtu + row * VT_STRIDE + d4) = vu;
        }
        __syncthreads();

        // ---- QK^T for this warp's 32 keys ----
        float acc[4][4];
        #pragma unroll
        for (int nb = 0; nb < 4; ++nb)
            acc[nb][0] = acc[nb][1] = acc[nb][2] = acc[nb][3] = 0.f;
        #pragma unroll
        for (int ks = 0; ks < 8; ++ks) {
            int kc = ks * 8 + tg;
            #pragma unroll
            for (int nb = 0; nb < 4; ++nb) {
                int key = nbase + nb * 8 + g;
                uint32_t b0 = ktu[key * KT_STRIDE + kc];
                uint32_t b1 = ktu[key * KT_STRIDE + kc + 4];
                mma_tf32(acc[nb], qa[ks][0], qa[ks][1], qa[ks][2], qa[ks][3], b0, b1);
            }
        }

        // ---- Epilogue: scale + edge + mask; write scores ----
        #pragma unroll
        for (int nb = 0; nb < 4; ++nb) {
            int col = t * BN + nbase + nb * 8 + 2 * tg;
            #pragma unroll
            for (int rr = 0; rr < 2; ++rr) {
                int r = rb * 16 + g + rr * 8;
                float2 e = *(const float2*)(Eg + (size_t)r * SS + col);
                int2  mv = *(const int2*)(Mg + (size_t)r * SS + col);
                float s0 = acc[nb][rr*2+0] * scale + e.x;
                float s1 = acc[nb][rr*2+1] * scale + e.y;
                s0 = mv.x ? -1e9f : s0;
                s1 = mv.y ? -1e9f : s1;
                acc[nb][rr*2+0] = s0;
                acc[nb][rr*2+1] = s1;
                *(float2*)(out_scores + (bhS + qbase + r) * SS + col) = make_float2(s0, s1);
            }
        }

        // ---- Online softmax update (per warp slice) ----
        float tm_g  = fmaxf(fmaxf(acc[0][0], acc[0][1]), fmaxf(acc[1][0], acc[1][1]));
        float tm_g8 = fmaxf(fmaxf(acc[0][2], acc[0][3]), fmaxf(acc[1][2], acc[1][3]));
        tm_g  = fmaxf(tm_g,  fmaxf(fmaxf(acc[2][0], acc[2][1]), fmaxf(acc[3][0], acc[3][1])));
        tm_g8 = fmaxf(tm_g8, fmaxf(fmaxf(acc[2][2], acc[2][3]), fmaxf(acc[3][2], acc[3][3])));
        tm_g  = fmaxf(tm_g,  __shfl_xor_sync(0xFFFFFFFFu, tm_g,  1));
        tm_g  = fmaxf(tm_g,  __shfl_xor_sync(0xFFFFFFFFu, tm_g,  2));
        tm_g8 = fmaxf(tm_g8, __shfl_xor_sync(0xFFFFFFFFu, tm_g8, 1));
        tm_g8 = fmaxf(tm_g8, __shfl_xor_sync(0xFFFFFFFFu, tm_g8, 2));

        float nm_g  = fmaxf(m_g,  tm_g);
        float nm_g8 = fmaxf(m_g8, tm_g8);
        float f_g   = __expf(m_g  - nm_g);
        float f_g8  = __expf(m_g8 - nm_g8);
        m_g = nm_g; m_g8 = nm_g8;

        float zs_g = 0.f, zs_g8 = 0.f;
        #pragma unroll
        for (int nb = 0; nb < 4; ++nb) {
            acc[nb][0] = __expf(acc[nb][0] - m_g);
            acc[nb][1] = __expf(acc[nb][1] - m_g);
            acc[nb][2] = __expf(acc[nb][2] - m_g8);
            acc[nb][3] = __expf(acc[nb][3] - m_g8);
            zs_g  += acc[nb][0] + acc[nb][1];
            zs_g8 += acc[nb][2] + acc[nb][3];
        }
        zs_g  += __shfl_xor_sync(0xFFFFFFFFu, zs_g,  1);
        zs_g  += __shfl_xor_sync(0xFFFFFFFFu, zs_g,  2);
        zs_g8 += __shfl_xor_sync(0xFFFFFFFFu, zs_g8, 1);
        zs_g8 += __shfl_xor_sync(0xFFFFFFFFu, zs_g8, 2);
        z_g  = z_g  * f_g  + zs_g;
        z_g8 = z_g8 * f_g8 + zs_g8;

        #pragma unroll
        for (int n = 0; n < 8; ++n) {
            cacc[n][0] *= f_g;  cacc[n][1] *= f_g;
            cacc[n][2] *= f_g8; cacc[n][3] *= f_g8;
        }

        // ---- PV: P C-frag -> A-frag via quad shuffles, mma over dims ----
        #pragma unroll
        for (int c = 0; c < 4; ++c) {
            int src0 = (g << 2) + (tg >> 1);
            int src1 = src0 + 2;
            float v00 = __shfl_sync(0xFFFFFFFFu, acc[c][0], src0);
            float v01 = __shfl_sync(0xFFFFFFFFu, acc[c][1], src0);
            float v10 = __shfl_sync(0xFFFFFFFFu, acc[c][2], src0);
            float v11 = __shfl_sync(0xFFFFFFFFu, acc[c][3], src0);
            float v20 = __shfl_sync(0xFFFFFFFFu, acc[c][0], src1);
            float v21 = __shfl_sync(0xFFFFFFFFu, acc[c][1], src1);
            float v30 = __shfl_sync(0xFFFFFFFFu, acc[c][2], src1);
            float v31 = __shfl_sync(0xFFFFFFFFu, acc[c][3], src1);
            bool odd = (tg & 1);
            uint32_t a0 = f2tf(odd ? v01 : v00);
            uint32_t a1 = f2tf(odd ? v11 : v10);
            uint32_t a2 = f2tf(odd ? v21 : v20);
            uint32_t a3 = f2tf(odd ? v31 : v30);

            int kr0 = nbase + c * 8 + tg;
            const uint32_t* v0p = vtu + kr0 * VT_STRIDE + g;
            const uint32_t* v1p = vtu + (kr0 + 4) * VT_STRIDE + g;
            #pragma unroll
            for (int n = 0; n < 8; ++n) {
                mma_tf32(cacc[n], a0, a1, a2, a3, v0p[n * 8], v1p[n * 8]);
            }
        }
    }

    __syncthreads();

    // ---- Write per-warp partials + stats (pbuf reuses kt+vt; stats reuse qs) ----
    float* pbuf   = kt;          // [16 warps][16 rows][PB_STRIDE] = 17408 floats
    float* sm_m   = qs;          // [16][16]
    float* sm_z   = qs + 256;    // [16][16]
    float* row_m  = qs + 512;    // [64]
    float* row_iz = qs + 576;    // [64]

    #pragma unroll
    for (int n = 0; n < 8; ++n) {
        pbuf[(w * 16 + g)     * PB_STRIDE + n * 8 + 2 * tg]     = cacc[n][0];
        pbuf[(w * 16 + g)     * PB_STRIDE + n * 8 + 2 * tg + 1] = cacc[n][1];
        pbuf[(w * 16 + g + 8) * PB_STRIDE + n * 8 + 2 * tg]     = cacc[n][2];
        pbuf[(w * 16 + g + 8) * PB_STRIDE + n * 8 + 2 * tg + 1] = cacc[n][3];
    }
    if (tg == 0) {
        sm_m[w * 16 + g]     = m_g;  sm_m[w * 16 + g + 8] = m_g8;
        sm_z[w * 16 + g]     = z_g;  sm_z[w * 16 + g + 8] = z_g8;
    }
    __syncthreads();

    // ---- Combine 4 key-slice warps per row -> ctx ----
    {
        int r  = tid >> 3;            // 0..63
        int c  = tid & 7;             // 0..7
        int d0 = c * 8;
        int lrb = r >> 4, lr = r & 15;

        float m = -1e30f;
        #pragma unroll
        for (int s = 0; s < 4; ++s)
            m = fmaxf(m, sm_m[(lrb * 4 + s) * 16 + lr]);
        float zt = 0.f;
        float val[8] = {0.f,0.f,0.f,0.f,0.f,0.f,0.f,0.f};
        #pragma unroll
        for (int s = 0; s < 4; ++s) {
            int ww = lrb * 4 + s;
            float ew = __expf(sm_m[ww * 16 + lr] - m);
            zt += sm_z[ww * 16 + lr] * ew;
            const float* pp = pbuf + (ww * 16 + lr) * PB_STRIDE + d0;
            #pragma unroll
            for (int j = 0; j < 8; ++j) val[j] += pp[j] * ew;
        }
        float iz = 1.0f / zt;
        float* op = out_ctx + (bhS + qbase + r) * DD + d0;
        *(float4*)(op)     = make_float4(val[0]*iz, val[1]*iz, val[2]*iz, val[3]*iz);
        *(float4*)(op + 4) = make_float4(val[4]*iz, val[5]*iz, val[6]*iz, val[7]*iz);
        if (c == 0) { row_m[r] = m; row_iz[r] = iz; }
    }
    __syncthreads();

    // ---- Phase C: attn = exp(scores - m) * 1/Z (scores L2-hot) ----
    {
        int r = tid >> 3;
        int c = tid & 7;
        float m  = row_m[r];
        float iz = row_iz[r];
        const float4* sv = (const float4*)(out_scores + (bhS + qbase + r) * SS);
        float4*       av = (float4*)(out_attn  + (bhS + qbase + r) * SS);
        #pragma unroll 4
        for (int k4 = c; k4 < SS / 4; k4 += 8) {
            float4 x = sv[k4];
            x.x = __expf(x.x - m) * iz;
            x.y = __expf(x.y - m) * iz;
            x.z = __expf(x.z - m) * iz;
            x.w = __expf(x.w - m) * iz;
            av[k4] = x;
        }
    }
}

extern "C" void kernel_launch(void* const* d_in, const int* in_sizes, int n_in,
                              void* d_out, int out_size)
{
    (void)in_sizes; (void)n_in; (void)out_size;
    const float* Q = (const float*)d_in[0];
    const float* K = (const float*)d_in[1];
    const float* V = (const float*)d_in[2];
    const int* mask = (const int*)d_in[3];
    const float* edge = (const float*)d_in[4];

    float* ctx = (float*)d_out;
    const size_t n_ctx  = (size_t)BB * HH * SS * DD;
    const size_t n_attn = (size_t)BB * HH * SS * SS;
    float* attn   = ctx + n_ctx;
    float* scores = attn + n_attn;

    const size_t smem_bytes = (size_t)SMEM_FLOATS * sizeof(float);
    cudaFuncSetAttribute(attn_flash64_kernel,
                         cudaFuncAttributeMaxDynamicSharedMemorySize,
                         (int)smem_bytes);

    dim3 grid(BB * HH, SS / BM);   // (32, 32); x fastest -> K/V + edge hot in L2
    attn_flash64_kernel<<<grid, THREADS, smem_bytes>>>(Q, K, V, mask, edge, ctx, attn, scores);
}

// round 16
// speedup vs baseline: 1.0294x; 1.0107x over previous
#include <cuda_runtime.h>
#include <cstdint>

#define BB 4
#define HH 8
#define SS 2048
#define DD 64
#define BM 64          // query rows per CTA
#define BN 128         // key cols per tile
#define NT (SS / BN)   // 16 tiles
#define THREADS 512

#define KT_STRIDE 68   // K tile row stride: frag banks 4g+tg distinct
#define VT_STRIDE 72   // V tile row stride: frag banks 8tg+g distinct
#define QS_STRIDE 68
#define PB_STRIDE 68

// smem floats: kt[128][68]=8704 + vt[128][72]=9216 + qs[64][68]=4352 = 22272 (89KB)
// pbuf (16 warps x 16 rows x 68 = 17408) reuses kt+vt; stats reuse qs.
#define SMEM_FLOATS (128 * KT_STRIDE + 128 * VT_STRIDE + BM * QS_STRIDE)

__device__ __forceinline__ uint32_t f2tf(float f) {
    uint32_t r;
    asm("cvt.rna.tf32.f32 %0, %1;" : "=r"(r) : "f"(f));
    return r;
}

__device__ __forceinline__ void mma_tf32(float acc[4],
                                         uint32_t a0, uint32_t a1, uint32_t a2, uint32_t a3,
                                         uint32_t b0, uint32_t b1) {
    asm volatile(
        "mma.sync.aligned.m16n8k8.row.col.f32.tf32.tf32.f32 "
        "{%0,%1,%2,%3}, {%4,%5,%6,%7}, {%8,%9}, {%0,%1,%2,%3};"
        : "+f"(acc[0]), "+f"(acc[1]), "+f"(acc[2]), "+f"(acc[3])
        : "r"(a0), "r"(a1), "r"(a2), "r"(a3), "r"(b0), "r"(b1));
}

__global__ __launch_bounds__(THREADS, 1)
void attn_flash64_kernel(const float* __restrict__ Q,
                         const float* __restrict__ K,
                         const float* __restrict__ V,
                         const int* __restrict__ mask,     // bool as int32
                         const float* __restrict__ edge,
                         float* __restrict__ out_ctx,
                         float* __restrict__ out_attn,
                         float* __restrict__ out_scores)
{
    extern __shared__ float smem[];
    float* kt = smem;                            // [128][KT_STRIDE] tf32 bits
    float* vt = kt + 128 * KT_STRIDE;            // [128][VT_STRIDE] tf32 bits
    float* qs = vt + 128 * VT_STRIDE;            // [64][QS_STRIDE]
    uint32_t* ktu = (uint32_t*)kt;
    uint32_t* vtu = (uint32_t*)vt;

    const int tid  = threadIdx.x;
    const int lane = tid & 31;
    const int w    = tid >> 5;          // 0..15
    const int rb   = w >> 2;            // row block 0..3 (16 rows each)
    const int ksl  = w & 3;             // key slice 0..3 (32 keys each)
    const int g    = lane >> 2;         // 0..7
    const int tg   = lane & 3;          // 0..3

    const int bh    = blockIdx.x;       // 0..31
    const int b     = bh >> 3;
    const int qbase = blockIdx.y * BM;

    const size_t bhS = (size_t)bh * SS;
    const float* Qg = Q + (bhS + qbase) * DD;
    const float* Kg = K + bhS * DD;
    const float* Vg = V + bhS * DD;
    const int*   Mg = mask + (bhS + qbase) * SS;
    const float* Eg = edge + ((size_t)b * SS + qbase) * SS;

    // ---- Load Q tile (64x64) ----
    #pragma unroll
    for (int p = 0; p < 2; ++p) {
        int f = tid + p * THREADS;
        int row = f >> 4, d4 = (f & 15) << 2;
        *(float4*)(qs + row * QS_STRIDE + d4) = ((const float4*)Qg)[f];
    }
    __syncthreads();

    // ---- Preload Q fragments (tf32); warp rows: rb*16 + g, + g+8 ----
    uint32_t qa[8][4];
    {
        const float* q0 = qs + (rb * 16 + g) * QS_STRIDE;
        const float* q1 = qs + (rb * 16 + g + 8) * QS_STRIDE;
        #pragma unroll
        for (int ks = 0; ks < 8; ++ks) {
            int kc = ks * 8 + tg;
            qa[ks][0] = f2tf(q0[kc]);
            qa[ks][1] = f2tf(q1[kc]);
            qa[ks][2] = f2tf(q0[kc + 4]);
            qa[ks][3] = f2tf(q1[kc + 4]);
        }
    }

    const float scale = 0.125f;  // 1/sqrt(64)
    const int nbase = ksl * 32;  // warp's 32-key slice within 128-key tile

    // Online softmax state (rows rb*16+g and rb*16+g+8, warp's key slice)
    float m_g = -1e30f, m_g8 = -1e30f;
    float z_g = 0.f, z_g8 = 0.f;
    float cacc[8][4];
    #pragma unroll
    for (int n = 0; n < 8; ++n)
        cacc[n][0] = cacc[n][1] = cacc[n][2] = cacc[n][3] = 0.f;

    for (int t = 0; t < NT; ++t) {
        __syncthreads();
        // Load K and V tiles (128x64), converting to tf32 bits at store
        const float4* ksrc = (const float4*)(Kg + (size_t)t * BN * DD);
        const float4* vsrc = (const float4*)(Vg + (size_t)t * BN * DD);
        #pragma unroll
        for (int p = 0; p < 4; ++p) {
            int f = tid + p * THREADS;
            int row = f >> 4, d4 = (f & 15) << 2;
            float4 kv = ksrc[f];
            float4 vv = vsrc[f];
            uint4 ku = make_uint4(f2tf(kv.x), f2tf(kv.y), f2tf(kv.z), f2tf(kv.w));
            uint4 vu = make_uint4(f2tf(vv.x), f2tf(vv.y), f2tf(vv.z), f2tf(vv.w));
            *(uint4*)(ktu + row * KT_STRIDE + d4) = ku;
            *(uint4*)(vtu + row * VT_STRIDE + d4) = vu;
        }
        __syncthreads();

        // ---- QK^T for this warp's 32 keys ----
        float acc[4][4];
        #pragma unroll
        for (int nb = 0; nb < 4; ++nb)
            acc[nb][0] = acc[nb][1] = acc[nb][2] = acc[nb][3] = 0.f;
        #pragma unroll
        for (int ks = 0; ks < 8; ++ks) {
            int kc = ks * 8 + tg;
            #pragma unroll
            for (int nb = 0; nb < 4; ++nb) {
                int key = nbase + nb * 8 + g;
                uint32_t b0 = ktu[key * KT_STRIDE + kc];
                uint32_t b1 = ktu[key * KT_STRIDE + kc + 4];
                mma_tf32(acc[nb], qa[ks][0], qa[ks][1], qa[ks][2], qa[ks][3], b0, b1);
            }
        }

        // ---- Epilogue: scale + edge + mask; write scores ----
        #pragma unroll
        for (int nb = 0; nb < 4; ++nb) {
            int col = t * BN + nbase + nb * 8 + 2 * tg;
            #pragma unroll
            for (int rr = 0; rr < 2; ++rr) {
                int r = rb * 16 + g + rr * 8;
                float2 e = *(const float2*)(Eg + (size_t)r * SS + col);
                int2  mv = *(const int2*)(Mg + (size_t)r * SS + col);
                float s0 = acc[nb][rr*2+0] * scale + e.x;
                float s1 = acc[nb][rr*2+1] * scale + e.y;
                s0 = mv.x ? -1e9f : s0;
                s1 = mv.y ? -1e9f : s1;
                acc[nb][rr*2+0] = s0;
                acc[nb][rr*2+1] = s1;
                *(float2*)(out_scores + (bhS + qbase + r) * SS + col) = make_float2(s0, s1);
            }
        }

        // ---- Online softmax update (per warp slice) ----
        float tm_g  = fmaxf(fmaxf(acc[0][0], acc[0][1]), fmaxf(acc[1][0], acc[1][1]));
        float tm_g8 = fmaxf(fmaxf(acc[0][2], acc[0][3]), fmaxf(acc[1][2], acc[1][3]));
        tm_g  = fmaxf(tm_g,  fmaxf(fmaxf(acc[2][0], acc[2][1]), fmaxf(acc[3][0], acc[3][1])));
        tm_g8 = fmaxf(tm_g8, fmaxf(fmaxf(acc[2][2], acc[2][3]), fmaxf(acc[3][2], acc[3][3])));
        tm_g  = fmaxf(tm_g,  __shfl_xor_sync(0xFFFFFFFFu, tm_g,  1));
        tm_g  = fmaxf(tm_g,  __shfl_xor_sync(0xFFFFFFFFu, tm_g,  2));
        tm_g8 = fmaxf(tm_g8, __shfl_xor_sync(0xFFFFFFFFu, tm_g8, 1));
        tm_g8 = fmaxf(tm_g8, __shfl_xor_sync(0xFFFFFFFFu, tm_g8, 2));

        float nm_g  = fmaxf(m_g,  tm_g);
        float nm_g8 = fmaxf(m_g8, tm_g8);
        float f_g   = __expf(m_g  - nm_g);
        float f_g8  = __expf(m_g8 - nm_g8);
        m_g = nm_g; m_g8 = nm_g8;

        float zs_g = 0.f, zs_g8 = 0.f;
        #pragma unroll
        for (int nb = 0; nb < 4; ++nb) {
            acc[nb][0] = __expf(acc[nb][0] - m_g);
            acc[nb][1] = __expf(acc[nb][1] - m_g);
            acc[nb][2] = __expf(acc[nb][2] - m_g8);
            acc[nb][3] = __expf(acc[nb][3] - m_g8);
            zs_g  += acc[nb][0] + acc[nb][1];
            zs_g8 += acc[nb][2] + acc[nb][3];
        }
        zs_g  += __shfl_xor_sync(0xFFFFFFFFu, zs_g,  1);
        zs_g  += __shfl_xor_sync(0xFFFFFFFFu, zs_g,  2);
        zs_g8 += __shfl_xor_sync(0xFFFFFFFFu, zs_g8, 1);
        zs_g8 += __shfl_xor_sync(0xFFFFFFFFu, zs_g8, 2);
        z_g  = z_g  * f_g  + zs_g;
        z_g8 = z_g8 * f_g8 + zs_g8;

        #pragma unroll
        for (int n = 0; n < 8; ++n) {
            cacc[n][0] *= f_g;  cacc[n][1] *= f_g;
            cacc[n][2] *= f_g8; cacc[n][3] *= f_g8;
        }

        // ---- PV: P C-frag -> A-frag via quad shuffles, mma over dims ----
        #pragma unroll
        for (int c = 0; c < 4; ++c) {
            int src0 = (g << 2) + (tg >> 1);
            int src1 = src0 + 2;
            float v00 = __shfl_sync(0xFFFFFFFFu, acc[c][0], src0);
            float v01 = __shfl_sync(0xFFFFFFFFu, acc[c][1], src0);
            float v10 = __shfl_sync(0xFFFFFFFFu, acc[c][2], src0);
            float v11 = __shfl_sync(0xFFFFFFFFu, acc[c][3], src0);
            float v20 = __shfl_sync(0xFFFFFFFFu, acc[c][0], src1);
            float v21 = __shfl_sync(0xFFFFFFFFu, acc[c][1], src1);
            float v30 = __shfl_sync(0xFFFFFFFFu, acc[c][2], src1);
            float v31 = __shfl_sync(0xFFFFFFFFu, acc[c][3], src1);
            bool odd = (tg & 1);
            uint32_t a0 = f2tf(odd ? v01 : v00);
            uint32_t a1 = f2tf(odd ? v11 : v10);
            uint32_t a2 = f2tf(odd ? v21 : v20);
            uint32_t a3 = f2tf(odd ? v31 : v30);

            int kr0 = nbase + c * 8 + tg;
            const uint32_t* v0p = vtu + kr0 * VT_STRIDE + g;
            const uint32_t* v1p = vtu + (kr0 + 4) * VT_STRIDE + g;
            #pragma unroll
            for (int n = 0; n < 8; ++n) {
                mma_tf32(cacc[n], a0, a1, a2, a3, v0p[n * 8], v1p[n * 8]);
            }
        }
    }

    __syncthreads();

    // ---- Write per-warp partials + stats (pbuf reuses kt+vt; stats reuse qs) ----
    float* pbuf   = kt;          // [16 warps][16 rows][PB_STRIDE] = 17408 floats
    float* sm_m   = qs;          // [16][16]
    float* sm_z   = qs + 256;    // [16][16]
    float* row_m  = qs + 512;    // [64]
    float* row_iz = qs + 576;    // [64]

    #pragma unroll
    for (int n = 0; n < 8; ++n) {
        pbuf[(w * 16 + g)     * PB_STRIDE + n * 8 + 2 * tg]     = cacc[n][0];
        pbuf[(w * 16 + g)     * PB_STRIDE + n * 8 + 2 * tg + 1] = cacc[n][1];
        pbuf[(w * 16 + g + 8) * PB_STRIDE + n * 8 + 2 * tg]     = cacc[n][2];
        pbuf[(w * 16 + g + 8) * PB_STRIDE + n * 8 + 2 * tg + 1] = cacc[n][3];
    }
    if (tg == 0) {
        sm_m[w * 16 + g]     = m_g;  sm_m[w * 16 + g + 8] = m_g8;
        sm_z[w * 16 + g]     = z_g;  sm_z[w * 16 + g + 8] = z_g8;
    }
    __syncthreads();

    // ---- Combine 4 key-slice warps per row -> ctx ----
    {
        int r  = tid >> 3;            // 0..63
        int c  = tid & 7;             // 0..7
        int d0 = c * 8;
        int lrb = r >> 4, lr = r & 15;

        float m = -1e30f;
        #pragma unroll
        for (int s = 0; s < 4; ++s)
            m = fmaxf(m, sm_m[(lrb * 4 + s) * 16 + lr]);
        float zt = 0.f;
        float val[8] = {0.f,0.f,0.f,0.f,0.f,0.f,0.f,0.f};
        #pragma unroll
        for (int s = 0; s < 4; ++s) {
            int ww = lrb * 4 + s;
            float ew = __expf(sm_m[ww * 16 + lr] - m);
            zt += sm_z[ww * 16 + lr] * ew;
            const float* pp = pbuf + (ww * 16 + lr) * PB_STRIDE + d0;
            #pragma unroll
            for (int j = 0; j < 8; ++j) val[j] += pp[j] * ew;
        }
        float iz = 1.0f / zt;
        float* op = out_ctx + (bhS + qbase + r) * DD + d0;
        *(float4*)(op)     = make_float4(val[0]*iz, val[1]*iz, val[2]*iz, val[3]*iz);
        *(float4*)(op + 4) = make_float4(val[4]*iz, val[5]*iz, val[6]*iz, val[7]*iz);
        if (c == 0) { row_m[r] = m; row_iz[r] = iz; }
    }
    __syncthreads();

    // ---- Phase C: attn = exp(scores - m) * 1/Z (scores L2-hot) ----
    {
        int r = tid >> 3;
        int c = tid & 7;
        float m  = row_m[r];
        float iz = row_iz[r];
        const float4* sv = (const float4*)(out_scores + (bhS + qbase + r) * SS);
        float4*       av = (float4*)(out_attn  + (bhS + qbase + r) * SS);
        #pragma unroll 4
        for (int k4 = c; k4 < SS / 4; k4 += 8) {
            float4 x = sv[k4];
            x.x = __expf(x.x - m) * iz;
            x.y = __expf(x.y - m) * iz;
            x.z = __expf(x.z - m) * iz;
            x.w = __expf(x.w - m) * iz;
            av[k4] = x;
        }
    }
}

extern "C" void kernel_launch(void* const* d_in, const int* in_sizes, int n_in,
                              void* d_out, int out_size)
{
    (void)in_sizes; (void)n_in; (void)out_size;
    const float* Q = (const float*)d_in[0];
    const float* K = (const float*)d_in[1];
    const float* V = (const float*)d_in[2];
    const int* mask = (const int*)d_in[3];
    const float* edge = (const float*)d_in[4];

    float* ctx = (float*)d_out;
    const size_t n_ctx  = (size_t)BB * HH * SS * DD;
    const size_t n_attn = (size_t)BB * HH * SS * SS;
    float* attn   = ctx + n_ctx;
    float* scores = attn + n_attn;

    const size_t smem_bytes = (size_t)SMEM_FLOATS * sizeof(float);
    cudaFuncSetAttribute(attn_flash64_kernel,
                         cudaFuncAttributeMaxDynamicSharedMemorySize,
                         (int)smem_bytes);

    dim3 grid(BB * HH, SS / BM);   // (32, 32); x fastest -> K/V + edge hot in L2
    attn_flash64_kernel<<<grid, THREADS, smem_bytes>>>(Q, K, V, mask, edge, ctx, attn, scores);
}